// round 12
// baseline (speedup 1.0000x reference)
#include <cuda_runtime.h>
#include <cuda_bf16.h>

#define NN 100000
#define NE 1200000
#define NG 512
#define D  64
#define NC 10
#define NB 391            // scan blocks = ceil(NN/256)
#define NCHUNK 6250       // NN/16 exactly
#define GEMM_BLOCKS 391
#define GEMM_WARPS (GEMM_BLOCKS * 8)
#define RPX 72            // bf16 smem row pad (144B): conflict-free frag loads
#define RPW 72

// ---------------- scratch (device globals; no allocation) ----------------
__device__ int   g_degi[NN];
__device__ float g_dinv[NN];
__device__ __nv_bfloat162 g_ybf[NN * 32];   // y rows bf16 (32 bf162 = 64 vals)
__device__ __nv_bfloat16  g_hbf[NN * D];    // layer-1 activations bf16
__device__ float g_pool1[NG * D];
__device__ float g_pool2[NG * D];
__device__ int   g_cnti[NG];
// CSR
__device__ int   g_scan[NN];
__device__ int   g_bsum[NB];
__device__ int   g_start[NN + 1];
__device__ int   g_pos[NN];
__device__ int   g_ecol[NE];

__device__ __forceinline__ void red_v4(float4* dst, float4 v) {
    asm volatile("red.global.add.v4.f32 [%0], {%1,%2,%3,%4};"
                 :: "l"(dst), "f"(v.x), "f"(v.y), "f"(v.z), "f"(v.w) : "memory");
}

__device__ __forceinline__ void mma16(float d[4], const unsigned a[4],
                                      const unsigned b[2]) {
    asm volatile(
        "mma.sync.aligned.m16n8k16.row.col.f32.bf16.bf16.f32 "
        "{%0,%1,%2,%3}, {%4,%5,%6,%7}, {%8,%9}, {%0,%1,%2,%3};"
        : "+f"(d[0]), "+f"(d[1]), "+f"(d[2]), "+f"(d[3])
        : "r"(a[0]), "r"(a[1]), "r"(a[2]), "r"(a[3]), "r"(b[0]), "r"(b[1]));
}

// ---------------- setup kernels ----------------

__global__ void k_init() {
    int i = blockIdx.x * blockDim.x + threadIdx.x;
    if (i < NN) g_degi[i] = 0;
    if (i < NG * D) { g_pool1[i] = 0.0f; g_pool2[i] = 0.0f; }
    if (i < NG) g_cnti[i] = 0;
}

__global__ void k_deg(const int* __restrict__ rows) {
    int e = blockIdx.x * blockDim.x + threadIdx.x;
    if (e >= NE) return;
    unsigned r = (unsigned)rows[e];
    if (r < NN) atomicAdd(&g_degi[r], 1);
}

// per-block inclusive scan of degrees; fused: dinv + per-graph counts
__global__ void k_scanA(const int* __restrict__ batch) {
    __shared__ int s[256];
    int t = threadIdx.x;
    int i = blockIdx.x * 256 + t;
    int d = (i < NN) ? g_degi[i] : 0;
    s[t] = d;
    if (i < NN) {
        g_dinv[i] = rsqrtf((float)d + 1.0f);   // +1 = self loop
        unsigned g = (unsigned)batch[i];
        if (g < NG) atomicAdd(&g_cnti[g], 1);
    }
    __syncthreads();
#pragma unroll
    for (int off = 1; off < 256; off <<= 1) {
        int v = (t >= off) ? s[t - off] : 0;
        __syncthreads();
        s[t] += v;
        __syncthreads();
    }
    if (i < NN) g_scan[i] = s[t];
    if (t == 255) g_bsum[blockIdx.x] = s[255];
}

// scanC (scanB folded in): each block sums g_bsum[0..b-1] itself
__global__ void k_scanC() {
    __shared__ int red[8];
    __shared__ int sboff;
    int t = threadIdx.x;
    int b = blockIdx.x;
    int partial = 0;
    for (int i = t; i < b; i += 256) partial += g_bsum[i];
#pragma unroll
    for (int off = 16; off; off >>= 1)
        partial += __shfl_xor_sync(0xffffffffu, partial, off);
    if ((t & 31) == 0) red[t >> 5] = partial;
    __syncthreads();
    if (t < 8) {
        int v = red[t];
#pragma unroll
        for (int off = 4; off; off >>= 1)
            v += __shfl_xor_sync(0xffu, v, off);
        if (t == 0) sboff = v;
    }
    __syncthreads();
    int i = b * 256 + t;
    if (i < NN) {
        int st = g_scan[i] - g_degi[i] + sboff;
        g_start[i] = st;
        g_pos[i] = st;
    }
    if (i == 0) g_start[NN] = NE;
}

__global__ void k_fill(const int* __restrict__ rows, const int* __restrict__ cols) {
    int e = blockIdx.x * blockDim.x + threadIdx.x;
    if (e >= NE) return;
    unsigned r = (unsigned)rows[e];
    if (r >= NN) return;
    int p = atomicAdd(&g_pos[r], 1);
    g_ecol[p] = cols[e];
}

// ---------------- tensor-core GEMM: g_ybf = bf16(dinv * (X W)) ----------------
__device__ __forceinline__ void stage_Wt(__nv_bfloat16* sWt,
                                         const float* __restrict__ W) {
    int t = threadIdx.x;
    for (int i = t; i < 4096; i += 256) {
        int k = i >> 6, n = i & 63;
        sWt[n * RPW + k] = __float2bfloat16(W[i]);
    }
    __syncthreads();
}

__device__ __forceinline__ void build_B(unsigned bfr[8][4][2],
                                        const __nv_bfloat16* sWt, int lane) {
#pragma unroll
    for (int nt = 0; nt < 8; nt++) {
        int n = nt * 8 + (lane >> 2);
#pragma unroll
        for (int ks = 0; ks < 4; ks++) {
            bfr[nt][ks][0] = *(const unsigned*)&sWt[n * RPW + ks * 16 + (lane & 3) * 2];
            bfr[nt][ks][1] = *(const unsigned*)&sWt[n * RPW + ks * 16 + 8 + (lane & 3) * 2];
        }
    }
}

__device__ __forceinline__ void mma_chunk(const __nv_bfloat16* myX,
                                          const unsigned bfr[8][4][2],
                                          int lane, int n0) {
    float dreg[8][4];
#pragma unroll
    for (int nt = 0; nt < 8; nt++)
#pragma unroll
        for (int j = 0; j < 4; j++) dreg[nt][j] = 0.0f;

#pragma unroll
    for (int ks = 0; ks < 4; ks++) {
        unsigned a[4];
        a[0] = *(const unsigned*)&myX[(lane >> 2) * RPX + ks * 16 + (lane & 3) * 2];
        a[1] = *(const unsigned*)&myX[((lane >> 2) + 8) * RPX + ks * 16 + (lane & 3) * 2];
        a[2] = *(const unsigned*)&myX[(lane >> 2) * RPX + ks * 16 + 8 + (lane & 3) * 2];
        a[3] = *(const unsigned*)&myX[((lane >> 2) + 8) * RPX + ks * 16 + 8 + (lane & 3) * 2];
#pragma unroll
        for (int nt = 0; nt < 8; nt++) mma16(dreg[nt], a, bfr[nt][ks]);
    }

    int r0 = n0 + (lane >> 2), r1 = r0 + 8;
    float s0 = g_dinv[r0];
    float s1 = g_dinv[r1];
#pragma unroll
    for (int nt = 0; nt < 8; nt++) {
        g_ybf[r0 * 32 + nt * 4 + (lane & 3)] =
            __floats2bfloat162_rn(s0 * dreg[nt][0], s0 * dreg[nt][1]);
        g_ybf[r1 * 32 + nt * 4 + (lane & 3)] =
            __floats2bfloat162_rn(s1 * dreg[nt][2], s1 * dreg[nt][3]);
    }
}

__global__ void __launch_bounds__(256) k_gemm1(const float* __restrict__ X,
                                               const float* __restrict__ W) {
    __shared__ __nv_bfloat16 sWt[64 * RPW];
    __shared__ __nv_bfloat16 sX[8][16 * RPX];
    int t = threadIdx.x, lane = t & 31, w = t >> 5;
    stage_Wt(sWt, W);
    unsigned bfr[8][4][2];
    build_B(bfr, sWt, lane);
    __nv_bfloat16* myX = sX[w];
    for (int ch = blockIdx.x * 8 + w; ch < NCHUNK; ch += GEMM_WARPS) {
        int n0 = ch * 16;
#pragma unroll
        for (int i = 0; i < 8; i++) {
            int idx = lane + 32 * i;           // 0..255
            int r = idx >> 4, c4 = idx & 15;
            float4 v = ((const float4*)X)[(n0 + r) * 16 + c4];
            *(__nv_bfloat162*)&myX[r * RPX + c4 * 4] = __floats2bfloat162_rn(v.x, v.y);
            *(__nv_bfloat162*)&myX[r * RPX + c4 * 4 + 2] = __floats2bfloat162_rn(v.z, v.w);
        }
        __syncwarp();
        mma_chunk(myX, bfr, lane, n0);
        __syncwarp();
    }
}

__global__ void __launch_bounds__(256) k_gemm2(const float* __restrict__ W) {
    __shared__ __nv_bfloat16 sWt[64 * RPW];
    __shared__ __nv_bfloat16 sX[8][16 * RPX];
    int t = threadIdx.x, lane = t & 31, w = t >> 5;
    stage_Wt(sWt, W);
    unsigned bfr[8][4][2];
    build_B(bfr, sWt, lane);
    __nv_bfloat16* myX = sX[w];
    for (int ch = blockIdx.x * 8 + w; ch < NCHUNK; ch += GEMM_WARPS) {
        int n0 = ch * 16;
#pragma unroll
        for (int i = 0; i < 4; i++) {
            int idx = lane + 32 * i;           // 0..127
            int r = idx >> 3, c8 = idx & 7;
            uint4 v = ((const uint4*)g_hbf)[(n0 + r) * 8 + c8];
            *(uint4*)&myX[r * RPX + c8 * 8] = v;
        }
        __syncwarp();
        mma_chunk(myX, bfr, lane, n0);
        __syncwarp();
    }
}

// ---------------- fused gather + finalize (bf16 messages, MLP-4) ----------------
__device__ __forceinline__ void acc_row(float4& acc, uint2 rv) {
    float2 g0 = __bfloat1622float2(*(__nv_bfloat162*)&rv.x);
    float2 g1 = __bfloat1622float2(*(__nv_bfloat162*)&rv.y);
    acc.x += g0.x; acc.y += g0.y; acc.z += g1.x; acc.w += g1.y;
}

__device__ __forceinline__ void gather_body(const float* __restrict__ b,
                                            const int* __restrict__ batch,
                                            float* __restrict__ pool,
                                            int store_h) {
    int idx = blockIdx.x * blockDim.x + threadIdx.x;
    int n = idx >> 4;
    int q = idx & 15;
    if (n >= NN) return;
    const uint2* y2 = (const uint2*)g_ybf;     // 16 x uint2 per row

    uint2 raw = y2[n * 16 + q];                // self loop term
    float4 acc;
    {
        float2 f0 = __bfloat1622float2(*(__nv_bfloat162*)&raw.x);
        float2 f1 = __bfloat1622float2(*(__nv_bfloat162*)&raw.y);
        acc = make_float4(f0.x, f0.y, f1.x, f1.y);
    }

    int s = g_start[n], e = g_start[n + 1];
    int ei = s;
    for (; ei + 4 <= e; ei += 4) {
        unsigned c0 = (unsigned)g_ecol[ei];
        unsigned c1 = (unsigned)g_ecol[ei + 1];
        unsigned c2 = (unsigned)g_ecol[ei + 2];
        unsigned c3 = (unsigned)g_ecol[ei + 3];
        uint2 r0 = y2[(c0 < NN ? c0 : 0u) * 16 + q];
        uint2 r1 = y2[(c1 < NN ? c1 : 0u) * 16 + q];
        uint2 r2 = y2[(c2 < NN ? c2 : 0u) * 16 + q];
        uint2 r3 = y2[(c3 < NN ? c3 : 0u) * 16 + q];
        if (c0 < NN) acc_row(acc, r0);
        if (c1 < NN) acc_row(acc, r1);
        if (c2 < NN) acc_row(acc, r2);
        if (c3 < NN) acc_row(acc, r3);
    }
    for (; ei < e; ei++) {
        unsigned c = (unsigned)g_ecol[ei];
        if (c < NN) acc_row(acc, y2[c * 16 + q]);
    }

    float sc = g_dinv[n];
    float4 bb = ((const float4*)b)[q];
    float4 h;
    h.x = fmaxf(sc * acc.x + bb.x, 0.0f);
    h.y = fmaxf(sc * acc.y + bb.y, 0.0f);
    h.z = fmaxf(sc * acc.z + bb.z, 0.0f);
    h.w = fmaxf(sc * acc.w + bb.w, 0.0f);
    if (store_h) {
        uint2 pk;
        __nv_bfloat162 p0 = __floats2bfloat162_rn(h.x, h.y);
        __nv_bfloat162 p1 = __floats2bfloat162_rn(h.z, h.w);
        pk.x = *(unsigned*)&p0; pk.y = *(unsigned*)&p1;
        *(uint2*)&g_hbf[n * 64 + q * 4] = pk;
    }
    unsigned g = (unsigned)batch[n];
    if (g < NG) red_v4(((float4*)pool) + g * 16 + q, h);
}

__global__ void k_gather1(const float* __restrict__ b, const int* __restrict__ batch) {
    gather_body(b, batch, g_pool1, 1);
}
__global__ void k_gather2(const float* __restrict__ b, const int* __restrict__ batch) {
    gather_body(b, batch, g_pool2, 0);
}

// ---------------- head ----------------
__global__ void k_head(const float* __restrict__ Wl, const float* __restrict__ bl,
                       float* __restrict__ out) {
    int g = blockIdx.x;
    int lane = threadIdx.x;  // 32
    float denom = fmaxf((float)g_cnti[g], 1.0f);
    float v0 = (g_pool1[g * D + lane] + g_pool2[g * D + lane]) / denom;
    float v1 = (g_pool1[g * D + 32 + lane] + g_pool2[g * D + 32 + lane]) / denom;
    float z = (lane < NC) ? bl[lane] : 0.0f;
#pragma unroll
    for (int d = 0; d < 32; d++) {
        float a0 = __shfl_sync(0xffffffffu, v0, d);
        float a1 = __shfl_sync(0xffffffffu, v1, d);
        if (lane < NC) z += a0 * Wl[d * NC + lane] + a1 * Wl[(d + 32) * NC + lane];
    }
    if (lane < NC) z = fmaxf(z, 0.0f);
    float zm = (lane < NC) ? z : -1e30f;
#pragma unroll
    for (int off = 16; off; off >>= 1)
        zm = fmaxf(zm, __shfl_xor_sync(0xffffffffu, zm, off));
    float e = (lane < NC) ? expf(z - zm) : 0.0f;
#pragma unroll
    for (int off = 16; off; off >>= 1)
        e += __shfl_xor_sync(0xffffffffu, e, off);
    if (lane < NC) out[g * NC + lane] = z - zm - logf(e);
}

// ---------------- launch ----------------

extern "C" void kernel_launch(void* const* d_in, const int* in_sizes, int n_in,
                              void* d_out, int out_size) {
    const float* x     = (const float*)d_in[0];
    const int*   eidx  = (const int*)d_in[1];    // int32 (JAX x64 disabled)
    const int*   batch = (const int*)d_in[2];
    const float* W1    = (const float*)d_in[3];
    const float* b1    = (const float*)d_in[4];
    const float* W2    = (const float*)d_in[5];
    const float* b2    = (const float*)d_in[6];
    const float* Wl    = (const float*)d_in[7];
    const float* bl    = (const float*)d_in[8];
    float* out = (float*)d_out;

    const int* rows = eidx;        // edge_index[0] = targets
    const int* cols = eidx + NE;   // edge_index[1] = sources

    k_init<<<(NN + 255) / 256, 256>>>();
    k_deg<<<(NE + 255) / 256, 256>>>(rows);

    // CSR build + dinv + counts (scanB folded into scanC)
    k_scanA<<<NB, 256>>>(batch);
    k_scanC<<<NB, 256>>>();
    k_fill<<<(NE + 255) / 256, 256>>>(rows, cols);

    // conv1
    k_gemm1<<<GEMM_BLOCKS, 256>>>(x, W1);
    k_gather1<<<(NN * 16 + 255) / 256, 256>>>(b1, batch);

    // conv2
    k_gemm2<<<GEMM_BLOCKS, 256>>>(W2);
    k_gather2<<<(NN * 16 + 255) / 256, 256>>>(b2, batch);

    // head
    k_head<<<NG, 32>>>(Wl, bl, out);
}

// round 13
// speedup vs baseline: 1.3978x; 1.3978x over previous
#include <cuda_runtime.h>
#include <cuda_bf16.h>

#define NN 100000
#define NE 1200000
#define NG 512
#define D  64
#define NC 10
#define NB 391            // scan blocks = ceil(NN/256)
#define NCHUNK 6250       // NN/16 exactly
#define GEMM_BLOCKS 391
#define GEMM_WARPS (GEMM_BLOCKS * 8)
#define RPX 72            // bf16 smem row pad (144B): conflict-free frag loads
#define RPW 72

// ---------------- scratch (device globals; no allocation) ----------------
__device__ int   g_degi[NN];
__device__ float g_dinv[NN];
__device__ __nv_bfloat162 g_ybf[NN * 32];   // y rows bf16 (32 bf162 = 64 vals)
__device__ __nv_bfloat16  g_hbf[NN * D];    // layer-1 activations bf16
__device__ float g_pool1[NG * D];
__device__ float g_pool2[NG * D];
__device__ int   g_cnti[NG];
// CSR
__device__ int   g_scan[NN];
__device__ int   g_bsum[NB];
__device__ int   g_start[NN + 1];
__device__ int   g_pos[NN];
__device__ int   g_ecol[NE];

__device__ __forceinline__ void red_v4(float4* dst, float4 v) {
    asm volatile("red.global.add.v4.f32 [%0], {%1,%2,%3,%4};"
                 :: "l"(dst), "f"(v.x), "f"(v.y), "f"(v.z), "f"(v.w) : "memory");
}

__device__ __forceinline__ void mma16(float d[4], const unsigned a[4],
                                      const unsigned b[2]) {
    asm volatile(
        "mma.sync.aligned.m16n8k16.row.col.f32.bf16.bf16.f32 "
        "{%0,%1,%2,%3}, {%4,%5,%6,%7}, {%8,%9}, {%0,%1,%2,%3};"
        : "+f"(d[0]), "+f"(d[1]), "+f"(d[2]), "+f"(d[3])
        : "r"(a[0]), "r"(a[1]), "r"(a[2]), "r"(a[3]), "r"(b[0]), "r"(b[1]));
}

// ---------------- setup kernels ----------------

__global__ void k_init() {
    int i = blockIdx.x * blockDim.x + threadIdx.x;
    if (i < NN) g_degi[i] = 0;
    if (i < NG * D) { g_pool1[i] = 0.0f; g_pool2[i] = 0.0f; }
    if (i < NG) g_cnti[i] = 0;
}

__global__ void k_deg(const int* __restrict__ rows) {
    int e = blockIdx.x * blockDim.x + threadIdx.x;
    if (e >= NE) return;
    unsigned r = (unsigned)rows[e];
    if (r < NN) atomicAdd(&g_degi[r], 1);
}

// per-block inclusive scan of degrees; fused: dinv + per-graph counts
__global__ void k_scanA(const int* __restrict__ batch) {
    __shared__ int s[256];
    int t = threadIdx.x;
    int i = blockIdx.x * 256 + t;
    int d = (i < NN) ? g_degi[i] : 0;
    s[t] = d;
    if (i < NN) {
        g_dinv[i] = rsqrtf((float)d + 1.0f);   // +1 = self loop
        unsigned g = (unsigned)batch[i];
        if (g < NG) atomicAdd(&g_cnti[g], 1);
    }
    __syncthreads();
#pragma unroll
    for (int off = 1; off < 256; off <<= 1) {
        int v = (t >= off) ? s[t - off] : 0;
        __syncthreads();
        s[t] += v;
        __syncthreads();
    }
    if (i < NN) g_scan[i] = s[t];
    if (t == 255) g_bsum[blockIdx.x] = s[255];
}

// scanC (scanB folded in): each block sums g_bsum[0..b-1] itself
__global__ void k_scanC() {
    __shared__ int red[8];
    __shared__ int sboff;
    int t = threadIdx.x;
    int b = blockIdx.x;
    int partial = 0;
    for (int i = t; i < b; i += 256) partial += g_bsum[i];
#pragma unroll
    for (int off = 16; off; off >>= 1)
        partial += __shfl_xor_sync(0xffffffffu, partial, off);
    if ((t & 31) == 0) red[t >> 5] = partial;
    __syncthreads();
    if (t < 8) {
        int v = red[t];
#pragma unroll
        for (int off = 4; off; off >>= 1)
            v += __shfl_xor_sync(0xffu, v, off);
        if (t == 0) sboff = v;
    }
    __syncthreads();
    int i = b * 256 + t;
    if (i < NN) {
        int st = g_scan[i] - g_degi[i] + sboff;
        g_start[i] = st;
        g_pos[i] = st;
    }
    if (i == 0) g_start[NN] = NE;
}

__global__ void k_fill(const int* __restrict__ rows, const int* __restrict__ cols) {
    int e = blockIdx.x * blockDim.x + threadIdx.x;
    if (e >= NE) return;
    unsigned r = (unsigned)rows[e];
    if (r >= NN) return;
    int p = atomicAdd(&g_pos[r], 1);
    g_ecol[p] = cols[e];
}

// ---------------- tensor-core GEMM: g_ybf = bf16(dinv * (X W)) ----------------
__device__ __forceinline__ void stage_Wt(__nv_bfloat16* sWt,
                                         const float* __restrict__ W) {
    int t = threadIdx.x;
    for (int i = t; i < 4096; i += 256) {
        int k = i >> 6, n = i & 63;
        sWt[n * RPW + k] = __float2bfloat16(W[i]);
    }
    __syncthreads();
}

__device__ __forceinline__ void build_B(unsigned bfr[8][4][2],
                                        const __nv_bfloat16* sWt, int lane) {
#pragma unroll
    for (int nt = 0; nt < 8; nt++) {
        int n = nt * 8 + (lane >> 2);
#pragma unroll
        for (int ks = 0; ks < 4; ks++) {
            bfr[nt][ks][0] = *(const unsigned*)&sWt[n * RPW + ks * 16 + (lane & 3) * 2];
            bfr[nt][ks][1] = *(const unsigned*)&sWt[n * RPW + ks * 16 + 8 + (lane & 3) * 2];
        }
    }
}

__device__ __forceinline__ void mma_chunk(const __nv_bfloat16* myX,
                                          const unsigned bfr[8][4][2],
                                          int lane, int n0) {
    float dreg[8][4];
#pragma unroll
    for (int nt = 0; nt < 8; nt++)
#pragma unroll
        for (int j = 0; j < 4; j++) dreg[nt][j] = 0.0f;

#pragma unroll
    for (int ks = 0; ks < 4; ks++) {
        unsigned a[4];
        a[0] = *(const unsigned*)&myX[(lane >> 2) * RPX + ks * 16 + (lane & 3) * 2];
        a[1] = *(const unsigned*)&myX[((lane >> 2) + 8) * RPX + ks * 16 + (lane & 3) * 2];
        a[2] = *(const unsigned*)&myX[(lane >> 2) * RPX + ks * 16 + 8 + (lane & 3) * 2];
        a[3] = *(const unsigned*)&myX[((lane >> 2) + 8) * RPX + ks * 16 + 8 + (lane & 3) * 2];
#pragma unroll
        for (int nt = 0; nt < 8; nt++) mma16(dreg[nt], a, bfr[nt][ks]);
    }

    int r0 = n0 + (lane >> 2), r1 = r0 + 8;
    float s0 = g_dinv[r0];
    float s1 = g_dinv[r1];
#pragma unroll
    for (int nt = 0; nt < 8; nt++) {
        g_ybf[r0 * 32 + nt * 4 + (lane & 3)] =
            __floats2bfloat162_rn(s0 * dreg[nt][0], s0 * dreg[nt][1]);
        g_ybf[r1 * 32 + nt * 4 + (lane & 3)] =
            __floats2bfloat162_rn(s1 * dreg[nt][2], s1 * dreg[nt][3]);
    }
}

__global__ void __launch_bounds__(256) k_gemm1(const float* __restrict__ X,
                                               const float* __restrict__ W) {
    __shared__ __nv_bfloat16 sWt[64 * RPW];
    __shared__ __nv_bfloat16 sX[8][16 * RPX];
    int t = threadIdx.x, lane = t & 31, w = t >> 5;
    stage_Wt(sWt, W);
    unsigned bfr[8][4][2];
    build_B(bfr, sWt, lane);
    __nv_bfloat16* myX = sX[w];
    for (int ch = blockIdx.x * 8 + w; ch < NCHUNK; ch += GEMM_WARPS) {
        int n0 = ch * 16;
#pragma unroll
        for (int i = 0; i < 8; i++) {
            int idx = lane + 32 * i;           // 0..255
            int r = idx >> 4, c4 = idx & 15;
            float4 v = ((const float4*)X)[(n0 + r) * 16 + c4];
            *(__nv_bfloat162*)&myX[r * RPX + c4 * 4] = __floats2bfloat162_rn(v.x, v.y);
            *(__nv_bfloat162*)&myX[r * RPX + c4 * 4 + 2] = __floats2bfloat162_rn(v.z, v.w);
        }
        __syncwarp();
        mma_chunk(myX, bfr, lane, n0);
        __syncwarp();
    }
}

__global__ void __launch_bounds__(256) k_gemm2(const float* __restrict__ W) {
    __shared__ __nv_bfloat16 sWt[64 * RPW];
    __shared__ __nv_bfloat16 sX[8][16 * RPX];
    int t = threadIdx.x, lane = t & 31, w = t >> 5;
    stage_Wt(sWt, W);
    unsigned bfr[8][4][2];
    build_B(bfr, sWt, lane);
    __nv_bfloat16* myX = sX[w];
    for (int ch = blockIdx.x * 8 + w; ch < NCHUNK; ch += GEMM_WARPS) {
        int n0 = ch * 16;
#pragma unroll
        for (int i = 0; i < 4; i++) {
            int idx = lane + 32 * i;           // 0..127
            int r = idx >> 3, c8 = idx & 7;
            uint4 v = ((const uint4*)g_hbf)[(n0 + r) * 8 + c8];
            *(uint4*)&myX[r * RPX + c8 * 8] = v;
        }
        __syncwarp();
        mma_chunk(myX, bfr, lane, n0);
        __syncwarp();
    }
}

// ---------------- fused gather + finalize (bf16 messages; simple loop) ----------------
__device__ __forceinline__ void gather_body(const float* __restrict__ b,
                                            const int* __restrict__ batch,
                                            float* __restrict__ pool,
                                            int store_h) {
    int idx = blockIdx.x * blockDim.x + threadIdx.x;
    int n = idx >> 4;
    int q = idx & 15;
    if (n >= NN) return;
    const uint2* y2 = (const uint2*)g_ybf;     // 16 x uint2 per row

    uint2 raw = y2[n * 16 + q];                // self loop term
    float2 f0 = __bfloat1622float2(*(__nv_bfloat162*)&raw.x);
    float2 f1 = __bfloat1622float2(*(__nv_bfloat162*)&raw.y);
    float4 acc = make_float4(f0.x, f0.y, f1.x, f1.y);

    int s = g_start[n], e = g_start[n + 1];
    for (int ei = s; ei < e; ei++) {
        unsigned c = (unsigned)g_ecol[ei];
        if (c < NN) {
            uint2 rv = y2[c * 16 + q];
            float2 g0 = __bfloat1622float2(*(__nv_bfloat162*)&rv.x);
            float2 g1 = __bfloat1622float2(*(__nv_bfloat162*)&rv.y);
            acc.x += g0.x; acc.y += g0.y; acc.z += g1.x; acc.w += g1.y;
        }
    }
    float sc = g_dinv[n];
    float4 bb = ((const float4*)b)[q];
    float4 h;
    h.x = fmaxf(sc * acc.x + bb.x, 0.0f);
    h.y = fmaxf(sc * acc.y + bb.y, 0.0f);
    h.z = fmaxf(sc * acc.z + bb.z, 0.0f);
    h.w = fmaxf(sc * acc.w + bb.w, 0.0f);
    if (store_h) {
        uint2 pk;
        __nv_bfloat162 p0 = __floats2bfloat162_rn(h.x, h.y);
        __nv_bfloat162 p1 = __floats2bfloat162_rn(h.z, h.w);
        pk.x = *(unsigned*)&p0; pk.y = *(unsigned*)&p1;
        *(uint2*)&g_hbf[n * 64 + q * 4] = pk;
    }
    unsigned g = (unsigned)batch[n];
    if (g < NG) red_v4(((float4*)pool) + g * 16 + q, h);
}

__global__ void k_gather1(const float* __restrict__ b, const int* __restrict__ batch) {
    gather_body(b, batch, g_pool1, 1);
}
__global__ void k_gather2(const float* __restrict__ b, const int* __restrict__ batch) {
    gather_body(b, batch, g_pool2, 0);
}

// ---------------- head ----------------
__global__ void k_head(const float* __restrict__ Wl, const float* __restrict__ bl,
                       float* __restrict__ out) {
    int g = blockIdx.x;
    int lane = threadIdx.x;  // 32
    float denom = fmaxf((float)g_cnti[g], 1.0f);
    float v0 = (g_pool1[g * D + lane] + g_pool2[g * D + lane]) / denom;
    float v1 = (g_pool1[g * D + 32 + lane] + g_pool2[g * D + 32 + lane]) / denom;
    float z = (lane < NC) ? bl[lane] : 0.0f;
#pragma unroll
    for (int d = 0; d < 32; d++) {
        float a0 = __shfl_sync(0xffffffffu, v0, d);
        float a1 = __shfl_sync(0xffffffffu, v1, d);
        if (lane < NC) z += a0 * Wl[d * NC + lane] + a1 * Wl[(d + 32) * NC + lane];
    }
    if (lane < NC) z = fmaxf(z, 0.0f);
    float zm = (lane < NC) ? z : -1e30f;
#pragma unroll
    for (int off = 16; off; off >>= 1)
        zm = fmaxf(zm, __shfl_xor_sync(0xffffffffu, zm, off));
    float e = (lane < NC) ? expf(z - zm) : 0.0f;
#pragma unroll
    for (int off = 16; off; off >>= 1)
        e += __shfl_xor_sync(0xffffffffu, e, off);
    if (lane < NC) out[g * NC + lane] = z - zm - logf(e);
}

// ---------------- launch ----------------

extern "C" void kernel_launch(void* const* d_in, const int* in_sizes, int n_in,
                              void* d_out, int out_size) {
    const float* x     = (const float*)d_in[0];
    const int*   eidx  = (const int*)d_in[1];    // int32 (JAX x64 disabled)
    const int*   batch = (const int*)d_in[2];
    const float* W1    = (const float*)d_in[3];
    const float* b1    = (const float*)d_in[4];
    const float* W2    = (const float*)d_in[5];
    const float* b2    = (const float*)d_in[6];
    const float* Wl    = (const float*)d_in[7];
    const float* bl    = (const float*)d_in[8];
    float* out = (float*)d_out;

    const int* rows = eidx;        // edge_index[0] = targets
    const int* cols = eidx + NE;   // edge_index[1] = sources

    k_init<<<(NN + 255) / 256, 256>>>();
    k_deg<<<(NE + 255) / 256, 256>>>(rows);

    // CSR build + dinv + counts (scanB folded into scanC)
    k_scanA<<<NB, 256>>>(batch);
    k_scanC<<<NB, 256>>>();
    k_fill<<<(NE + 255) / 256, 256>>>(rows, cols);

    // conv1
    k_gemm1<<<GEMM_BLOCKS, 256>>>(x, W1);
    k_gather1<<<(NN * 16 + 255) / 256, 256>>>(b1, batch);

    // conv2
    k_gemm2<<<GEMM_BLOCKS, 256>>>(W2);
    k_gather2<<<(NN * 16 + 255) / 256, 256>>>(b2, batch);

    // head
    k_head<<<NG, 32>>>(Wl, bl, out);
}